// round 1
// baseline (speedup 1.0000x reference)
#include <cuda_runtime.h>
#include <math.h>

#define BATCH 32
#define QLEN 300
#define BQ (BATCH*QLEN)        // 9600
#define D 256
#define NH 8
#define HD 32
#define S_TOT 8400
#define SP 12
#define FF 1024
#define LN_EPS 1e-5f

// ---------------- scratch (static device globals; no dynamic alloc) ----------
__device__ float g_hq[BQ*D];       // hs+pos, later reused as o-proj output
__device__ float g_q[BQ*D];
__device__ float g_k[BQ*D];
__device__ float g_v[BQ*D];
__device__ float g_attn[BQ*D];
__device__ float g_res[BQ*D];      // second_residual (post sa-LN)
__device__ float g_offs[BQ*192];
__device__ float g_awl[BQ*96];
__device__ float g_aw[BQ*96];
__device__ float g_ca[BQ*D];
__device__ float g_cat[BQ*512];
__device__ float g_gates[BQ*512];
__device__ float g_h2[BQ*D];
__device__ float g_ffn1[BQ*FF];
__device__ float g_ffn2[BQ*D];

// ---------------- elementwise ------------------------------------------------
__global__ void add_kernel(const float* __restrict__ a, const float* __restrict__ b,
                           float* __restrict__ o, int n) {
    int i = blockIdx.x * blockDim.x + threadIdx.x;
    if (i < n) o[i] = a[i] + b[i];
}

__global__ void concat_kernel(const float* __restrict__ a, const float* __restrict__ b,
                              float* __restrict__ o, int rows) {
    int i = blockIdx.x * blockDim.x + threadIdx.x;
    if (i >= rows * 512) return;
    int row = i >> 9;
    int c = i & 511;
    o[i] = (c < 256) ? a[row * 256 + c] : b[row * 256 + (c - 256)];
}

// ---------------- generic tiled SGEMM with fused epilogue --------------------
// C[M,N] = act((A[M,K] @ B[K,N] + bias[N]) * alpha)
// act: 0 = none, 1 = relu, 2 = sigmoid.  M % 64 == 0, K % 16 == 0 assumed.
__global__ void sgemm(const float* __restrict__ A, const float* __restrict__ B,
                      const float* __restrict__ bias, float* __restrict__ C,
                      int M, int N, int K, float alpha, int act) {
    __shared__ float As[16][64];
    __shared__ float Bs[16][64];
    int t = threadIdx.x;
    int m0 = blockIdx.y * 64;
    int n0 = blockIdx.x * 64;
    int ty = t >> 4, tx = t & 15;
    float acc[4][4] = {};
    for (int k0 = 0; k0 < K; k0 += 16) {
#pragma unroll
        for (int i = 0; i < 4; i++) {
            int e = t + i * 256;
            int m = e >> 4, k = e & 15;
            As[k][m] = A[(long)(m0 + m) * K + k0 + k];
        }
#pragma unroll
        for (int i = 0; i < 4; i++) {
            int e = t + i * 256;
            int k = e >> 6, n = e & 63;
            Bs[k][n] = (n0 + n < N) ? B[(long)(k0 + k) * N + n0 + n] : 0.f;
        }
        __syncthreads();
#pragma unroll
        for (int kk = 0; kk < 16; kk++) {
            float a[4], b[4];
#pragma unroll
            for (int i = 0; i < 4; i++) a[i] = As[kk][ty * 4 + i];
#pragma unroll
            for (int j = 0; j < 4; j++) b[j] = Bs[kk][tx * 4 + j];
#pragma unroll
            for (int i = 0; i < 4; i++)
#pragma unroll
                for (int j = 0; j < 4; j++)
                    acc[i][j] = fmaf(a[i], b[j], acc[i][j]);
        }
        __syncthreads();
    }
#pragma unroll
    for (int i = 0; i < 4; i++) {
        int row = m0 + ty * 4 + i;
#pragma unroll
        for (int j = 0; j < 4; j++) {
            int col = n0 + tx * 4 + j;
            if (col < N) {
                float v = (acc[i][j] + bias[col]) * alpha;
                if (act == 1) v = fmaxf(v, 0.f);
                else if (act == 2) v = 1.f / (1.f + __expf(-v));
                C[(long)row * N + col] = v;
            }
        }
    }
}

// ---------------- self-attention (online softmax, warp per query) ------------
__global__ void attn_kernel(const float* __restrict__ Qm, const float* __restrict__ Km,
                            const float* __restrict__ Vm, float* __restrict__ O) {
    __shared__ float ks[64 * HD];
    __shared__ float vs[64 * HD];
    int t = threadIdx.x;
    int warp = t >> 5, lane = t & 31;
    int bh = blockIdx.y;
    int b = bh >> 3, h = bh & 7;
    int q = blockIdx.x * 8 + warp;
    bool active = q < QLEN;
    long base = (long)b * QLEN * D + h * HD;
    float qv = active ? Qm[base + (long)q * D + lane] : 0.f;
    float m = -1e30f, l = 0.f, acc = 0.f;
    for (int kt = 0; kt < QLEN; kt += 64) {
        int n = min(64, QLEN - kt);
        __syncthreads();
#pragma unroll
        for (int i = 0; i < 8; i++) {
            int e = t + i * 256;
            int kk = e >> 5, d = e & 31;
            if (kk < n) {
                ks[e] = Km[base + (long)(kt + kk) * D + d];
                vs[e] = Vm[base + (long)(kt + kk) * D + d];
            }
        }
        __syncthreads();
        if (active) {
            for (int kk = 0; kk < n; kk++) {
                float s = qv * ks[kk * HD + lane];
#pragma unroll
                for (int off = 16; off > 0; off >>= 1)
                    s += __shfl_xor_sync(0xffffffffu, s, off);
                float nm = fmaxf(m, s);
                float sc = __expf(m - nm);
                float p = __expf(s - nm);
                l = l * sc + p;
                acc = acc * sc + p * vs[kk * HD + lane];
                m = nm;
            }
        }
    }
    if (active) O[base + (long)q * D + lane] = acc / l;
}

// ---------------- layernorm helpers ------------------------------------------
__device__ __forceinline__ float block_sum256(float v) {
    __shared__ float sh[8];
#pragma unroll
    for (int off = 16; off > 0; off >>= 1)
        v += __shfl_xor_sync(0xffffffffu, v, off);
    int t = threadIdx.x;
    if ((t & 31) == 0) sh[t >> 5] = v;
    __syncthreads();
    if (t == 0) {
        float s = 0.f;
        for (int i = 0; i < 8; i++) s += sh[i];
        sh[0] = s;
    }
    __syncthreads();
    float r = sh[0];
    __syncthreads();
    return r;
}

__device__ __forceinline__ void ln_write(float x, const float* w, const float* bb,
                                         float* O, int row) {
    int t = threadIdx.x;
    float mean = block_sum256(x) * (1.f / D);
    float d_ = x - mean;
    float var = block_sum256(d_ * d_) * (1.f / D);
    O[(long)row * D + t] = d_ * rsqrtf(var + LN_EPS) * w[t] + bb[t];
}

__global__ void ln_add(const float* __restrict__ A, const float* __restrict__ Bv,
                       const float* __restrict__ w, const float* __restrict__ bb,
                       float* __restrict__ O) {
    int row = blockIdx.x, t = threadIdx.x;
    float x = A[(long)row * D + t] + Bv[(long)row * D + t];
    ln_write(x, w, bb, O, row);
}

__global__ void gate_ln(const float* __restrict__ gates, const float* __restrict__ res,
                        const float* __restrict__ ca, const float* __restrict__ w,
                        const float* __restrict__ bb, float* __restrict__ O) {
    int row = blockIdx.x, t = threadIdx.x;
    float g1 = gates[(long)row * 512 + t];
    float g2 = gates[(long)row * 512 + 256 + t];
    float x = g1 * res[(long)row * D + t] + g2 * ca[(long)row * D + t];
    ln_write(x, w, bb, O, row);
}

// ---------------- aw softmax over SP=12 --------------------------------------
__global__ void softmax12(const float* __restrict__ in, float* __restrict__ out, int rows) {
    int r = blockIdx.x * blockDim.x + threadIdx.x;
    if (r >= rows) return;
    const float* p = in + (long)r * SP;
    float* o = out + (long)r * SP;
    float mx = -1e30f;
#pragma unroll
    for (int i = 0; i < SP; i++) mx = fmaxf(mx, p[i]);
    float e[SP], s = 0.f;
#pragma unroll
    for (int i = 0; i < SP; i++) { e[i] = __expf(p[i] - mx); s += e[i]; }
    float inv = 1.f / s;
#pragma unroll
    for (int i = 0; i < SP; i++) o[i] = e[i] * inv;
}

// ---------------- deformable bilinear sampling -------------------------------
__global__ void sample_kernel(const float* __restrict__ enc, const float* __restrict__ ref,
                              const float* __restrict__ offs, const float* __restrict__ aw,
                              float* __restrict__ ca) {
    int bq = blockIdx.x;
    int b = bq / QLEN;
    int t = threadIdx.x;
    int h = t >> 5, lane = t & 31;
    const float* rp = ref + (long)bq * 4;
    float rx = rp[0], ry = rp[1], rw = rp[2], rh = rp[3];
    const float* op = offs + (long)bq * 192 + h * 24;
    const float* ap = aw + (long)bq * 96 + h * 12;
    const float* eb = enc + (long)b * S_TOT * D + h * HD + lane;
    float acc = 0.f;
#pragma unroll
    for (int p = 0; p < SP; p++) {
        int lvl = p >> 2;
        int Wl = (lvl == 0) ? 80 : (lvl == 1) ? 40 : 20;
        int Hl = Wl;
        int s0 = (lvl == 0) ? 0 : (lvl == 1) ? 6400 : 8000;
        float ox = op[p * 2], oy = op[p * 2 + 1];
        float a = ap[p];
        // offset = offs * (1/4) * ref_wh * 0.5 ; grid-sample coord = loc*W - 0.5
        float gx = (rx + ox * 0.125f * rw) * (float)Wl - 0.5f;
        float gy = (ry + oy * 0.125f * rh) * (float)Hl - 0.5f;
        float x0f = floorf(gx), y0f = floorf(gy);
        float fx = gx - x0f, fy = gy - y0f;
        int x0 = (int)x0f, y0 = (int)y0f;
        int x1 = x0 + 1, y1 = y0 + 1;
        float w00 = (1.f - fx) * (1.f - fy) * a;
        float w10 = fx * (1.f - fy) * a;
        float w01 = (1.f - fx) * fy * a;
        float w11 = fx * fy * a;
        bool vx0 = (x0 >= 0) & (x0 < Wl), vx1 = (x1 >= 0) & (x1 < Wl);
        bool vy0 = (y0 >= 0) & (y0 < Hl), vy1 = (y1 >= 0) & (y1 < Hl);
        if (vx0 & vy0) acc += w00 * eb[(long)(s0 + y0 * Wl + x0) * D];
        if (vx1 & vy0) acc += w10 * eb[(long)(s0 + y0 * Wl + x1) * D];
        if (vx0 & vy1) acc += w01 * eb[(long)(s0 + y1 * Wl + x0) * D];
        if (vx1 & vy1) acc += w11 * eb[(long)(s0 + y1 * Wl + x1) * D];
    }
    ca[(long)bq * D + h * HD + lane] = acc;
}

// ---------------- host orchestration -----------------------------------------
extern "C" void kernel_launch(void* const* d_in, const int* in_sizes, int n_in,
                              void* d_out, int out_size) {
    const float* hs    = (const float*)d_in[0];
    const float* pos   = (const float*)d_in[1];
    const float* ref   = (const float*)d_in[2];
    const float* enc   = (const float*)d_in[3];
    const float* q_w   = (const float*)d_in[4];
    const float* q_b   = (const float*)d_in[5];
    const float* k_w   = (const float*)d_in[6];
    const float* k_b   = (const float*)d_in[7];
    const float* v_w   = (const float*)d_in[8];
    const float* v_b   = (const float*)d_in[9];
    const float* o_w   = (const float*)d_in[10];
    const float* o_b   = (const float*)d_in[11];
    const float* sa_ln_w = (const float*)d_in[12];
    const float* sa_ln_b = (const float*)d_in[13];
    const float* off_w = (const float*)d_in[14];
    const float* off_b = (const float*)d_in[15];
    const float* aw_w  = (const float*)d_in[16];
    const float* aw_b  = (const float*)d_in[17];
    const float* gate_w = (const float*)d_in[18];
    const float* gate_b = (const float*)d_in[19];
    const float* gate_ln_w = (const float*)d_in[20];
    const float* gate_ln_b = (const float*)d_in[21];
    const float* fc1_w = (const float*)d_in[22];
    const float* fc1_b = (const float*)d_in[23];
    const float* fc2_w = (const float*)d_in[24];
    const float* fc2_b = (const float*)d_in[25];
    const float* fin_ln_w = (const float*)d_in[26];
    const float* fin_ln_b = (const float*)d_in[27];
    float* out = (float*)d_out;

    float *p_hq, *p_q, *p_k, *p_v, *p_attn, *p_res, *p_offs, *p_awl, *p_aw,
          *p_ca, *p_cat, *p_gates, *p_h2, *p_ffn1, *p_ffn2;
    cudaGetSymbolAddress((void**)&p_hq, g_hq);
    cudaGetSymbolAddress((void**)&p_q, g_q);
    cudaGetSymbolAddress((void**)&p_k, g_k);
    cudaGetSymbolAddress((void**)&p_v, g_v);
    cudaGetSymbolAddress((void**)&p_attn, g_attn);
    cudaGetSymbolAddress((void**)&p_res, g_res);
    cudaGetSymbolAddress((void**)&p_offs, g_offs);
    cudaGetSymbolAddress((void**)&p_awl, g_awl);
    cudaGetSymbolAddress((void**)&p_aw, g_aw);
    cudaGetSymbolAddress((void**)&p_ca, g_ca);
    cudaGetSymbolAddress((void**)&p_cat, g_cat);
    cudaGetSymbolAddress((void**)&p_gates, g_gates);
    cudaGetSymbolAddress((void**)&p_h2, g_h2);
    cudaGetSymbolAddress((void**)&p_ffn1, g_ffn1);
    cudaGetSymbolAddress((void**)&p_ffn2, g_ffn2);

    const float scaling = 0.17677669529663687f; // 32^-0.5
    dim3 blk(256);

    // hq = hs + pos
    add_kernel<<<BQ * D / 256, blk>>>(hs, pos, p_hq, BQ * D);

    // q/k/v projections
    sgemm<<<dim3(4, 150), blk>>>(p_hq, q_w, q_b, p_q, BQ, D, D, scaling, 0);
    sgemm<<<dim3(4, 150), blk>>>(p_hq, k_w, k_b, p_k, BQ, D, D, 1.f, 0);
    sgemm<<<dim3(4, 150), blk>>>(hs,   v_w, v_b, p_v, BQ, D, D, 1.f, 0);

    // self-attention
    attn_kernel<<<dim3(38, BATCH * NH), blk>>>(p_q, p_k, p_v, p_attn);

    // o projection (into g_hq, now dead) + residual LN
    sgemm<<<dim3(4, 150), blk>>>(p_attn, o_w, o_b, p_hq, BQ, D, D, 1.f, 0);
    ln_add<<<BQ, blk>>>(hs, p_hq, sa_ln_w, sa_ln_b, p_res);

    // deformable projections
    sgemm<<<dim3(3, 150), blk>>>(p_res, off_w, off_b, p_offs, BQ, 192, D, 1.f, 0);
    sgemm<<<dim3(2, 150), blk>>>(p_res, aw_w, aw_b, p_awl, BQ, 96, D, 1.f, 0);
    softmax12<<<(BQ * NH + 255) / 256, blk>>>(p_awl, p_aw, BQ * NH);

    // bilinear sampling -> ca
    sample_kernel<<<BQ, blk>>>(enc, ref, p_offs, p_aw, p_ca);

    // gate
    concat_kernel<<<BQ * 512 / 256, blk>>>(p_res, p_ca, p_cat, BQ);
    sgemm<<<dim3(8, 150), blk>>>(p_cat, gate_w, gate_b, p_gates, BQ, 512, 512, 1.f, 2);
    gate_ln<<<BQ, blk>>>(p_gates, p_res, p_ca, gate_ln_w, gate_ln_b, p_h2);

    // FFN
    sgemm<<<dim3(16, 150), blk>>>(p_h2, fc1_w, fc1_b, p_ffn1, BQ, FF, D, 1.f, 1);
    sgemm<<<dim3(4, 150), blk>>>(p_ffn1, fc2_w, fc2_b, p_ffn2, BQ, D, FF, 1.f, 0);

    // final LN -> out
    ln_add<<<BQ, blk>>>(p_h2, p_ffn2, fin_ln_w, fin_ln_b, out);
}

// round 2
// speedup vs baseline: 1.6533x; 1.6533x over previous
#include <cuda_runtime.h>
#include <math.h>
#include <stdint.h>

#define BATCH 32
#define QLEN 300
#define BQ (BATCH*QLEN)        // 9600
#define D 256
#define NH 8
#define HD 32
#define S_TOT 8400
#define SP 12
#define FF 1024
#define LN_EPS 1e-5f

// ---------------- scratch (static device globals; no dynamic alloc) ----------
__device__ float g_hq[BQ*D];       // hs+pos, later reused as o-proj output
__device__ float g_q[BQ*D];
__device__ float g_k[BQ*D];
__device__ float g_v[BQ*D];
__device__ float g_attn[BQ*D];
__device__ float g_res[BQ*D];      // second_residual (post sa-LN)
__device__ float g_offs[BQ*192];
__device__ float g_awl[BQ*96];
__device__ float g_aw[BQ*96];
__device__ float g_ca[BQ*D];
__device__ float g_cat[BQ*512];
__device__ float g_gates[BQ*512];
__device__ float g_h2[BQ*D];
__device__ float g_ffn1[BQ*FF];
__device__ float g_ffn2[BQ*D];

// ---------------- elementwise ------------------------------------------------
__global__ void add_kernel(const float* __restrict__ a, const float* __restrict__ b,
                           float* __restrict__ o, int n) {
    int i = blockIdx.x * blockDim.x + threadIdx.x;
    if (i < n) o[i] = a[i] + b[i];
}

__global__ void concat_kernel(const float* __restrict__ a, const float* __restrict__ b,
                              float* __restrict__ o, int rows) {
    int i = blockIdx.x * blockDim.x + threadIdx.x;
    if (i >= rows * 512) return;
    int row = i >> 9;
    int c = i & 511;
    o[i] = (c < 256) ? a[row * 256 + c] : b[row * 256 + (c - 256)];
}

// ---------------- tf32 tensor-core GEMM --------------------------------------
// C[M,N] = act((A[M,K] @ B[K,N] + bias[N]) * alpha)
// act: 0=none, 1=relu, 2=sigmoid. M%128==0, K%32==0 assumed; N%4==0.
// Tiles: CTA 128x128x32, 8 warps of 64x32 (2x4), mma.m16n8k8 tf32.
// Smem: A stride 36 floats, B stride 136 floats (both conflict-free for frag loads).
#define TM 128
#define TN 128
#define TK 32
#define AS_STRIDE 36
#define BS_STRIDE 136
#define A_TILE_F (TM*AS_STRIDE)              // 4608 floats
#define B_TILE_F (TK*BS_STRIDE)              // 4352 floats
#define STAGE_F  (A_TILE_F + B_TILE_F)       // 8960 floats = 35840 B
#define GEMM_SMEM_BYTES (2*STAGE_F*4)        // 71680 B

__device__ __forceinline__ uint32_t f2tf(float f) {
    uint32_t r; asm("cvt.rna.tf32.f32 %0, %1;" : "=r"(r) : "f"(f)); return r;
}

__device__ __forceinline__ float epi(float v, float b, float alpha, int act) {
    v = (v + b) * alpha;
    if (act == 1) v = fmaxf(v, 0.f);
    else if (act == 2) v = 1.f / (1.f + __expf(-v));
    return v;
}

__global__ __launch_bounds__(256)
void tgemm(const float* __restrict__ A, const float* __restrict__ B,
           const float* __restrict__ bias, float* __restrict__ C,
           int M, int N, int K, float alpha, int act) {
    extern __shared__ float sm[];
    int t = threadIdx.x;
    int m0 = blockIdx.y * TM;
    int n0 = blockIdx.x * TN;
    int lane = t & 31, w = t >> 5;
    int gid = lane >> 2, tid4 = lane & 3;
    int wm = w >> 2, wn = w & 3;

    int arow = t >> 3;            // + i*32
    int ac4  = (t & 7) * 4;
    int brow = t >> 5;            // + i*8
    int bc4  = (t & 31) * 4;

    const int nk = K / TK;

    auto issue = [&](int kt, int stage) {
        float* As = sm + stage * STAGE_F;
        float* Bs = As + A_TILE_F;
        int k0 = kt * TK;
#pragma unroll
        for (int i = 0; i < 4; i++) {
            int r = arow + i * 32;
            const float* src = A + (long)(m0 + r) * K + k0 + ac4;
            uint32_t dst = (uint32_t)__cvta_generic_to_shared(As + r * AS_STRIDE + ac4);
            asm volatile("cp.async.cg.shared.global [%0], [%1], 16;" :: "r"(dst), "l"(src));
        }
#pragma unroll
        for (int i = 0; i < 4; i++) {
            int r = brow + i * 8;
            int col = n0 + bc4;
            int sz = (col < N) ? 16 : 0;
            const float* src = B + (sz ? ((long)(k0 + r) * N + col) : 0);
            uint32_t dst = (uint32_t)__cvta_generic_to_shared(Bs + r * BS_STRIDE + bc4);
            asm volatile("cp.async.cg.shared.global [%0], [%1], 16, %2;"
                         :: "r"(dst), "l"(src), "r"(sz));
        }
        asm volatile("cp.async.commit_group;");
    };

    float c[4][4][4];
#pragma unroll
    for (int i = 0; i < 4; i++)
#pragma unroll
        for (int j = 0; j < 4; j++)
#pragma unroll
            for (int k = 0; k < 4; k++) c[i][j][k] = 0.f;

    issue(0, 0);
    for (int kt = 0; kt < nk; kt++) {
        if (kt + 1 < nk) {
            issue(kt + 1, (kt + 1) & 1);
            asm volatile("cp.async.wait_group 1;");
        } else {
            asm volatile("cp.async.wait_group 0;");
        }
        __syncthreads();
        const float* As = sm + (kt & 1) * STAGE_F;
        const float* Bs = As + A_TILE_F;
#pragma unroll
        for (int kk = 0; kk < 4; kk++) {
            int ks = kk * 8;
            uint32_t a[4][4], b[4][2];
#pragma unroll
            for (int mt = 0; mt < 4; mt++) {
                int r = wm * 64 + mt * 16 + gid;
                a[mt][0] = f2tf(As[r * AS_STRIDE + ks + tid4]);
                a[mt][1] = f2tf(As[(r + 8) * AS_STRIDE + ks + tid4]);
                a[mt][2] = f2tf(As[r * AS_STRIDE + ks + tid4 + 4]);
                a[mt][3] = f2tf(As[(r + 8) * AS_STRIDE + ks + tid4 + 4]);
            }
#pragma unroll
            for (int nt = 0; nt < 4; nt++) {
                int cc = wn * 32 + nt * 8 + gid;
                b[nt][0] = f2tf(Bs[(ks + tid4) * BS_STRIDE + cc]);
                b[nt][1] = f2tf(Bs[(ks + tid4 + 4) * BS_STRIDE + cc]);
            }
#pragma unroll
            for (int mt = 0; mt < 4; mt++)
#pragma unroll
                for (int nt = 0; nt < 4; nt++) {
                    asm volatile(
                        "mma.sync.aligned.m16n8k8.row.col.f32.tf32.tf32.f32 "
                        "{%0,%1,%2,%3}, {%4,%5,%6,%7}, {%8,%9}, {%0,%1,%2,%3};"
                        : "+f"(c[mt][nt][0]), "+f"(c[mt][nt][1]),
                          "+f"(c[mt][nt][2]), "+f"(c[mt][nt][3])
                        : "r"(a[mt][0]), "r"(a[mt][1]), "r"(a[mt][2]), "r"(a[mt][3]),
                          "r"(b[nt][0]), "r"(b[nt][1]));
                }
        }
        __syncthreads();
    }

    // epilogue
#pragma unroll
    for (int mt = 0; mt < 4; mt++) {
        int r0 = m0 + wm * 64 + mt * 16 + gid;
#pragma unroll
        for (int nt = 0; nt < 4; nt++) {
            int col = n0 + wn * 32 + nt * 8 + tid4 * 2;
            if (col < N) {
                float b0 = bias[col], b1 = bias[col + 1];
                float2 v0, v1;
                v0.x = epi(c[mt][nt][0], b0, alpha, act);
                v0.y = epi(c[mt][nt][1], b1, alpha, act);
                v1.x = epi(c[mt][nt][2], b0, alpha, act);
                v1.y = epi(c[mt][nt][3], b1, alpha, act);
                *(float2*)&C[(long)r0 * N + col] = v0;
                *(float2*)&C[(long)(r0 + 8) * N + col] = v1;
            }
        }
    }
}

// ---------------- self-attention (online softmax, warp per query) ------------
__global__ void attn_kernel(const float* __restrict__ Qm, const float* __restrict__ Km,
                            const float* __restrict__ Vm, float* __restrict__ O) {
    __shared__ float ks[64 * HD];
    __shared__ float vs[64 * HD];
    int t = threadIdx.x;
    int warp = t >> 5, lane = t & 31;
    int bh = blockIdx.y;
    int b = bh >> 3, h = bh & 7;
    int q = blockIdx.x * 8 + warp;
    bool active = q < QLEN;
    long base = (long)b * QLEN * D + h * HD;
    float qv = active ? Qm[base + (long)q * D + lane] : 0.f;
    float m = -1e30f, l = 0.f, acc = 0.f;
    for (int kt = 0; kt < QLEN; kt += 64) {
        int n = min(64, QLEN - kt);
        __syncthreads();
#pragma unroll
        for (int i = 0; i < 8; i++) {
            int e = t + i * 256;
            int kk = e >> 5, d = e & 31;
            if (kk < n) {
                ks[e] = Km[base + (long)(kt + kk) * D + d];
                vs[e] = Vm[base + (long)(kt + kk) * D + d];
            }
        }
        __syncthreads();
        if (active) {
            for (int kk = 0; kk < n; kk++) {
                float s = qv * ks[kk * HD + lane];
#pragma unroll
                for (int off = 16; off > 0; off >>= 1)
                    s += __shfl_xor_sync(0xffffffffu, s, off);
                float nm = fmaxf(m, s);
                float sc = __expf(m - nm);
                float p = __expf(s - nm);
                l = l * sc + p;
                acc = acc * sc + p * vs[kk * HD + lane];
                m = nm;
            }
        }
    }
    if (active) O[base + (long)q * D + lane] = acc / l;
}

// ---------------- layernorm helpers ------------------------------------------
__device__ __forceinline__ float block_sum256(float v) {
    __shared__ float sh[8];
#pragma unroll
    for (int off = 16; off > 0; off >>= 1)
        v += __shfl_xor_sync(0xffffffffu, v, off);
    int t = threadIdx.x;
    if ((t & 31) == 0) sh[t >> 5] = v;
    __syncthreads();
    if (t == 0) {
        float s = 0.f;
        for (int i = 0; i < 8; i++) s += sh[i];
        sh[0] = s;
    }
    __syncthreads();
    float r = sh[0];
    __syncthreads();
    return r;
}

__device__ __forceinline__ void ln_write(float x, const float* w, const float* bb,
                                         float* O, int row) {
    int t = threadIdx.x;
    float mean = block_sum256(x) * (1.f / D);
    float d_ = x - mean;
    float var = block_sum256(d_ * d_) * (1.f / D);
    O[(long)row * D + t] = d_ * rsqrtf(var + LN_EPS) * w[t] + bb[t];
}

__global__ void ln_add(const float* __restrict__ A, const float* __restrict__ Bv,
                       const float* __restrict__ w, const float* __restrict__ bb,
                       float* __restrict__ O) {
    int row = blockIdx.x, t = threadIdx.x;
    float x = A[(long)row * D + t] + Bv[(long)row * D + t];
    ln_write(x, w, bb, O, row);
}

__global__ void gate_ln(const float* __restrict__ gates, const float* __restrict__ res,
                        const float* __restrict__ ca, const float* __restrict__ w,
                        const float* __restrict__ bb, float* __restrict__ O) {
    int row = blockIdx.x, t = threadIdx.x;
    float g1 = gates[(long)row * 512 + t];
    float g2 = gates[(long)row * 512 + 256 + t];
    float x = g1 * res[(long)row * D + t] + g2 * ca[(long)row * D + t];
    ln_write(x, w, bb, O, row);
}

// ---------------- aw softmax over SP=12 --------------------------------------
__global__ void softmax12(const float* __restrict__ in, float* __restrict__ out, int rows) {
    int r = blockIdx.x * blockDim.x + threadIdx.x;
    if (r >= rows) return;
    const float* p = in + (long)r * SP;
    float* o = out + (long)r * SP;
    float mx = -1e30f;
#pragma unroll
    for (int i = 0; i < SP; i++) mx = fmaxf(mx, p[i]);
    float e[SP], s = 0.f;
#pragma unroll
    for (int i = 0; i < SP; i++) { e[i] = __expf(p[i] - mx); s += e[i]; }
    float inv = 1.f / s;
#pragma unroll
    for (int i = 0; i < SP; i++) o[i] = e[i] * inv;
}

// ---------------- deformable bilinear sampling -------------------------------
__global__ void sample_kernel(const float* __restrict__ enc, const float* __restrict__ ref,
                              const float* __restrict__ offs, const float* __restrict__ aw,
                              float* __restrict__ ca) {
    int bq = blockIdx.x;
    int b = bq / QLEN;
    int t = threadIdx.x;
    int h = t >> 5, lane = t & 31;
    const float* rp = ref + (long)bq * 4;
    float rx = rp[0], ry = rp[1], rw = rp[2], rh = rp[3];
    const float* op = offs + (long)bq * 192 + h * 24;
    const float* ap = aw + (long)bq * 96 + h * 12;
    const float* eb = enc + (long)b * S_TOT * D + h * HD + lane;
    float acc = 0.f;
#pragma unroll
    for (int p = 0; p < SP; p++) {
        int lvl = p >> 2;
        int Wl = (lvl == 0) ? 80 : (lvl == 1) ? 40 : 20;
        int Hl = Wl;
        int s0 = (lvl == 0) ? 0 : (lvl == 1) ? 6400 : 8000;
        float ox = op[p * 2], oy = op[p * 2 + 1];
        float a = ap[p];
        float gx = (rx + ox * 0.125f * rw) * (float)Wl - 0.5f;
        float gy = (ry + oy * 0.125f * rh) * (float)Hl - 0.5f;
        float x0f = floorf(gx), y0f = floorf(gy);
        float fx = gx - x0f, fy = gy - y0f;
        int x0 = (int)x0f, y0 = (int)y0f;
        int x1 = x0 + 1, y1 = y0 + 1;
        float w00 = (1.f - fx) * (1.f - fy) * a;
        float w10 = fx * (1.f - fy) * a;
        float w01 = (1.f - fx) * fy * a;
        float w11 = fx * fy * a;
        bool vx0 = (x0 >= 0) & (x0 < Wl), vx1 = (x1 >= 0) & (x1 < Wl);
        bool vy0 = (y0 >= 0) & (y0 < Hl), vy1 = (y1 >= 0) & (y1 < Hl);
        if (vx0 & vy0) acc += w00 * eb[(long)(s0 + y0 * Wl + x0) * D];
        if (vx1 & vy0) acc += w10 * eb[(long)(s0 + y0 * Wl + x1) * D];
        if (vx0 & vy1) acc += w01 * eb[(long)(s0 + y1 * Wl + x0) * D];
        if (vx1 & vy1) acc += w11 * eb[(long)(s0 + y1 * Wl + x1) * D];
    }
    ca[(long)bq * D + h * HD + lane] = acc;
}

// ---------------- host orchestration -----------------------------------------
static void launch_gemm(const float* A, const float* B, const float* bias, float* C,
                        int M, int N, int K, float alpha, int act) {
    dim3 grid((N + TN - 1) / TN, M / TM);
    tgemm<<<grid, 256, GEMM_SMEM_BYTES>>>(A, B, bias, C, M, N, K, alpha, act);
}

extern "C" void kernel_launch(void* const* d_in, const int* in_sizes, int n_in,
                              void* d_out, int out_size) {
    const float* hs    = (const float*)d_in[0];
    const float* pos   = (const float*)d_in[1];
    const float* ref   = (const float*)d_in[2];
    const float* enc   = (const float*)d_in[3];
    const float* q_w   = (const float*)d_in[4];
    const float* q_b   = (const float*)d_in[5];
    const float* k_w   = (const float*)d_in[6];
    const float* k_b   = (const float*)d_in[7];
    const float* v_w   = (const float*)d_in[8];
    const float* v_b   = (const float*)d_in[9];
    const float* o_w   = (const float*)d_in[10];
    const float* o_b   = (const float*)d_in[11];
    const float* sa_ln_w = (const float*)d_in[12];
    const float* sa_ln_b = (const float*)d_in[13];
    const float* off_w = (const float*)d_in[14];
    const float* off_b = (const float*)d_in[15];
    const float* aw_w  = (const float*)d_in[16];
    const float* aw_b  = (const float*)d_in[17];
    const float* gate_w = (const float*)d_in[18];
    const float* gate_b = (const float*)d_in[19];
    const float* gate_ln_w = (const float*)d_in[20];
    const float* gate_ln_b = (const float*)d_in[21];
    const float* fc1_w = (const float*)d_in[22];
    const float* fc1_b = (const float*)d_in[23];
    const float* fc2_w = (const float*)d_in[24];
    const float* fc2_b = (const float*)d_in[25];
    const float* fin_ln_w = (const float*)d_in[26];
    const float* fin_ln_b = (const float*)d_in[27];
    float* out = (float*)d_out;

    float *p_hq, *p_q, *p_k, *p_v, *p_attn, *p_res, *p_offs, *p_awl, *p_aw,
          *p_ca, *p_cat, *p_gates, *p_h2, *p_ffn1, *p_ffn2;
    cudaGetSymbolAddress((void**)&p_hq, g_hq);
    cudaGetSymbolAddress((void**)&p_q, g_q);
    cudaGetSymbolAddress((void**)&p_k, g_k);
    cudaGetSymbolAddress((void**)&p_v, g_v);
    cudaGetSymbolAddress((void**)&p_attn, g_attn);
    cudaGetSymbolAddress((void**)&p_res, g_res);
    cudaGetSymbolAddress((void**)&p_offs, g_offs);
    cudaGetSymbolAddress((void**)&p_awl, g_awl);
    cudaGetSymbolAddress((void**)&p_aw, g_aw);
    cudaGetSymbolAddress((void**)&p_ca, g_ca);
    cudaGetSymbolAddress((void**)&p_cat, g_cat);
    cudaGetSymbolAddress((void**)&p_gates, g_gates);
    cudaGetSymbolAddress((void**)&p_h2, g_h2);
    cudaGetSymbolAddress((void**)&p_ffn1, g_ffn1);
    cudaGetSymbolAddress((void**)&p_ffn2, g_ffn2);

    cudaFuncSetAttribute(tgemm, cudaFuncAttributeMaxDynamicSharedMemorySize,
                         GEMM_SMEM_BYTES);

    const float scaling = 0.17677669529663687f; // 32^-0.5
    dim3 blk(256);

    // hq = hs + pos
    add_kernel<<<BQ * D / 256, blk>>>(hs, pos, p_hq, BQ * D);

    // q/k/v projections
    launch_gemm(p_hq, q_w, q_b, p_q, BQ, D, D, scaling, 0);
    launch_gemm(p_hq, k_w, k_b, p_k, BQ, D, D, 1.f, 0);
    launch_gemm(hs,   v_w, v_b, p_v, BQ, D, D, 1.f, 0);

    // self-attention
    attn_kernel<<<dim3(38, BATCH * NH), blk>>>(p_q, p_k, p_v, p_attn);

    // o projection + residual LN
    launch_gemm(p_attn, o_w, o_b, p_hq, BQ, D, D, 1.f, 0);
    ln_add<<<BQ, blk>>>(hs, p_hq, sa_ln_w, sa_ln_b, p_res);

    // deformable projections
    launch_gemm(p_res, off_w, off_b, p_offs, BQ, 192, D, 1.f, 0);
    launch_gemm(p_res, aw_w, aw_b, p_awl, BQ, 96, D, 1.f, 0);
    softmax12<<<(BQ * NH + 255) / 256, blk>>>(p_awl, p_aw, BQ * NH);

    // bilinear sampling -> ca
    sample_kernel<<<BQ, blk>>>(enc, ref, p_offs, p_aw, p_ca);

    // gate
    concat_kernel<<<BQ * 512 / 256, blk>>>(p_res, p_ca, p_cat, BQ);
    launch_gemm(p_cat, gate_w, gate_b, p_gates, BQ, 512, 512, 1.f, 2);
    gate_ln<<<BQ, blk>>>(p_gates, p_res, p_ca, gate_ln_w, gate_ln_b, p_h2);

    // FFN
    launch_gemm(p_h2, fc1_w, fc1_b, p_ffn1, BQ, FF, D, 1.f, 1);
    launch_gemm(p_ffn1, fc2_w, fc2_b, p_ffn2, BQ, D, FF, 1.f, 0);

    // final LN -> out
    ln_add<<<BQ, blk>>>(p_h2, p_ffn2, fin_ln_w, fin_ln_b, out);
}

// round 3
// speedup vs baseline: 4.0689x; 2.4611x over previous
#include <cuda_runtime.h>
#include <math.h>
#include <stdint.h>

#define BATCH 32
#define QLEN 300
#define BQ (BATCH*QLEN)        // 9600
#define D 256
#define NH 8
#define HD 32
#define S_TOT 8400
#define SP 12
#define FF 1024
#define LN_EPS 1e-5f

// ---------------- scratch (static device globals; no dynamic alloc) ----------
__device__ float g_hq[BQ*D];
__device__ float g_q[BQ*D];
__device__ float g_k[BQ*D];
__device__ float g_v[BQ*D];
__device__ float g_attn[BQ*D];
__device__ float g_res[BQ*D];
__device__ float g_offs[BQ*192];
__device__ float g_awl[BQ*96];
__device__ float g_aw[BQ*96];
__device__ float g_ca[BQ*D];
__device__ float g_cat[BQ*512];
__device__ float g_gates[BQ*512];
__device__ float g_h2[BQ*D];
__device__ float g_ffn1[BQ*FF];
__device__ float g_ffn2[BQ*D];

__device__ __forceinline__ uint32_t f2tf(float f) {
    uint32_t r; asm("cvt.rna.tf32.f32 %0, %1;" : "=r"(r) : "f"(f)); return r;
}

#define MMA_TF32(C, A0, A1, A2, A3, B0, B1)                                  \
    asm volatile(                                                            \
        "mma.sync.aligned.m16n8k8.row.col.f32.tf32.tf32.f32 "                \
        "{%0,%1,%2,%3}, {%4,%5,%6,%7}, {%8,%9}, {%0,%1,%2,%3};"              \
        : "+f"((C)[0]), "+f"((C)[1]), "+f"((C)[2]), "+f"((C)[3])             \
        : "r"(A0), "r"(A1), "r"(A2), "r"(A3), "r"(B0), "r"(B1))

// ---------------- elementwise ------------------------------------------------
__global__ void add_kernel(const float* __restrict__ a, const float* __restrict__ b,
                           float* __restrict__ o, int n) {
    int i = blockIdx.x * blockDim.x + threadIdx.x;
    if (i < n) o[i] = a[i] + b[i];
}

__global__ void concat_kernel(const float* __restrict__ a, const float* __restrict__ b,
                              float* __restrict__ o, int rows) {
    int i = blockIdx.x * blockDim.x + threadIdx.x;
    if (i >= rows * 512) return;
    int row = i >> 9;
    int c = i & 511;
    o[i] = (c < 256) ? a[row * 256 + c] : b[row * 256 + (c - 256)];
}

// ---------------- tf32 tensor-core GEMM --------------------------------------
#define TM 128
#define TN 128
#define TK 32
#define AS_STRIDE 36
#define BS_STRIDE 136
#define A_TILE_F (TM*AS_STRIDE)
#define B_TILE_F (TK*BS_STRIDE)
#define STAGE_F  (A_TILE_F + B_TILE_F)
#define GEMM_SMEM_BYTES (2*STAGE_F*4)

__device__ __forceinline__ float epi(float v, float b, float alpha, int act) {
    v = (v + b) * alpha;
    if (act == 1) v = fmaxf(v, 0.f);
    else if (act == 2) v = 1.f / (1.f + __expf(-v));
    return v;
}

__global__ __launch_bounds__(256)
void tgemm(const float* __restrict__ A, const float* __restrict__ B,
           const float* __restrict__ bias, float* __restrict__ C,
           int M, int N, int K, float alpha, int act) {
    extern __shared__ float sm[];
    int t = threadIdx.x;
    int m0 = blockIdx.y * TM;
    int n0 = blockIdx.x * TN;
    int lane = t & 31, w = t >> 5;
    int gid = lane >> 2, tid4 = lane & 3;
    int wm = w >> 2, wn = w & 3;

    int arow = t >> 3;
    int ac4  = (t & 7) * 4;
    int brow = t >> 5;
    int bc4  = (t & 31) * 4;

    const int nk = K / TK;

    auto issue = [&](int kt, int stage) {
        float* As = sm + stage * STAGE_F;
        float* Bs = As + A_TILE_F;
        int k0 = kt * TK;
#pragma unroll
        for (int i = 0; i < 4; i++) {
            int r = arow + i * 32;
            const float* src = A + (long)(m0 + r) * K + k0 + ac4;
            uint32_t dst = (uint32_t)__cvta_generic_to_shared(As + r * AS_STRIDE + ac4);
            asm volatile("cp.async.cg.shared.global [%0], [%1], 16;" :: "r"(dst), "l"(src));
        }
#pragma unroll
        for (int i = 0; i < 4; i++) {
            int r = brow + i * 8;
            int col = n0 + bc4;
            int sz = (col < N) ? 16 : 0;
            const float* src = B + (sz ? ((long)(k0 + r) * N + col) : 0);
            uint32_t dst = (uint32_t)__cvta_generic_to_shared(Bs + r * BS_STRIDE + bc4);
            asm volatile("cp.async.cg.shared.global [%0], [%1], 16, %2;"
                         :: "r"(dst), "l"(src), "r"(sz));
        }
        asm volatile("cp.async.commit_group;");
    };

    float c[4][4][4];
#pragma unroll
    for (int i = 0; i < 4; i++)
#pragma unroll
        for (int j = 0; j < 4; j++)
#pragma unroll
            for (int k = 0; k < 4; k++) c[i][j][k] = 0.f;

    issue(0, 0);
    for (int kt = 0; kt < nk; kt++) {
        if (kt + 1 < nk) {
            issue(kt + 1, (kt + 1) & 1);
            asm volatile("cp.async.wait_group 1;");
        } else {
            asm volatile("cp.async.wait_group 0;");
        }
        __syncthreads();
        const float* As = sm + (kt & 1) * STAGE_F;
        const float* Bs = As + A_TILE_F;
#pragma unroll
        for (int kk = 0; kk < 4; kk++) {
            int ks = kk * 8;
            uint32_t a[4][4], b[4][2];
#pragma unroll
            for (int mt = 0; mt < 4; mt++) {
                int r = wm * 64 + mt * 16 + gid;
                a[mt][0] = f2tf(As[r * AS_STRIDE + ks + tid4]);
                a[mt][1] = f2tf(As[(r + 8) * AS_STRIDE + ks + tid4]);
                a[mt][2] = f2tf(As[r * AS_STRIDE + ks + tid4 + 4]);
                a[mt][3] = f2tf(As[(r + 8) * AS_STRIDE + ks + tid4 + 4]);
            }
#pragma unroll
            for (int nt = 0; nt < 4; nt++) {
                int cc = wn * 32 + nt * 8 + gid;
                b[nt][0] = f2tf(Bs[(ks + tid4) * BS_STRIDE + cc]);
                b[nt][1] = f2tf(Bs[(ks + tid4 + 4) * BS_STRIDE + cc]);
            }
#pragma unroll
            for (int mt = 0; mt < 4; mt++)
#pragma unroll
                for (int nt = 0; nt < 4; nt++)
                    MMA_TF32(c[mt][nt], a[mt][0], a[mt][1], a[mt][2], a[mt][3],
                             b[nt][0], b[nt][1]);
        }
        __syncthreads();
    }

#pragma unroll
    for (int mt = 0; mt < 4; mt++) {
        int r0 = m0 + wm * 64 + mt * 16 + gid;
#pragma unroll
        for (int nt = 0; nt < 4; nt++) {
            int col = n0 + wn * 32 + nt * 8 + tid4 * 2;
            if (col < N) {
                float b0 = bias[col], b1 = bias[col + 1];
                float2 v0, v1;
                v0.x = epi(c[mt][nt][0], b0, alpha, act);
                v0.y = epi(c[mt][nt][1], b1, alpha, act);
                v1.x = epi(c[mt][nt][2], b0, alpha, act);
                v1.y = epi(c[mt][nt][3], b1, alpha, act);
                *(float2*)&C[(long)r0 * N + col] = v0;
                *(float2*)&C[(long)(r0 + 8) * N + col] = v1;
            }
        }
    }
}

// ---------------- flash attention (tf32 MMA) ---------------------------------
// CTA: 128 threads (4 warps), 64 queries of one (b,h). Key loop: 5 tiles of 64.
#define AT_QS 36
#define AT_KS 36
#define AT_VS 40

__global__ __launch_bounds__(128)
void flash_attn(const float* __restrict__ Qm, const float* __restrict__ Km,
                const float* __restrict__ Vm, float* __restrict__ O) {
    __shared__ float Qs[64 * AT_QS];
    __shared__ float Ks[64 * AT_KS];
    __shared__ float Vs[64 * AT_VS];
    int t = threadIdx.x;
    int lane = t & 31, w = t >> 5;
    int gid = lane >> 2, tid4 = lane & 3;
    int qt = blockIdx.x;           // 0..4
    int bh = blockIdx.y;           // 0..255
    int b = bh >> 3, h = bh & 7;
    long base = (long)b * QLEN * D + h * HD;

    // load Q tile 64x32
#pragma unroll
    for (int i = 0; i < 4; i++) {
        int e = t + i * 128;
        int row = e >> 3, c4 = (e & 7) * 4;
        int q = qt * 64 + row;
        float4 v = make_float4(0.f, 0.f, 0.f, 0.f);
        if (q < QLEN) v = *(const float4*)&Qm[base + (long)q * D + c4];
        *(float4*)&Qs[row * AT_QS + c4] = v;
    }
    __syncthreads();

    // hoist Q fragments (tf32)
    uint32_t aq[4][4];
    int r0 = w * 16 + gid;
#pragma unroll
    for (int k4 = 0; k4 < 4; k4++) {
        int ks = k4 * 8;
        aq[k4][0] = f2tf(Qs[r0 * AT_QS + ks + tid4]);
        aq[k4][1] = f2tf(Qs[(r0 + 8) * AT_QS + ks + tid4]);
        aq[k4][2] = f2tf(Qs[r0 * AT_QS + ks + tid4 + 4]);
        aq[k4][3] = f2tf(Qs[(r0 + 8) * AT_QS + ks + tid4 + 4]);
    }

    float m0 = -1e30f, m1 = -1e30f, l0 = 0.f, l1 = 0.f;
    float co[4][4] = {};

    for (int kt = 0; kt < 5; kt++) {
        __syncthreads();
#pragma unroll
        for (int i = 0; i < 4; i++) {
            int e = t + i * 128;
            int row = e >> 3, c4 = (e & 7) * 4;
            int kk = kt * 64 + row;
            float4 v = make_float4(0.f, 0.f, 0.f, 0.f);
            float4 u = make_float4(0.f, 0.f, 0.f, 0.f);
            if (kk < QLEN) {
                v = *(const float4*)&Km[base + (long)kk * D + c4];
                u = *(const float4*)&Vm[base + (long)kk * D + c4];
            }
            *(float4*)&Ks[row * AT_KS + c4] = v;
            *(float4*)&Vs[row * AT_VS + c4] = u;
        }
        __syncthreads();

        // S = Q @ K^T
        float cs[8][4];
#pragma unroll
        for (int nt = 0; nt < 8; nt++)
#pragma unroll
            for (int j = 0; j < 4; j++) cs[nt][j] = 0.f;
#pragma unroll
        for (int k4 = 0; k4 < 4; k4++) {
            int ks = k4 * 8;
#pragma unroll
            for (int nt = 0; nt < 8; nt++) {
                int key = nt * 8 + gid;
                uint32_t b0 = f2tf(Ks[key * AT_KS + ks + tid4]);
                uint32_t b1 = f2tf(Ks[key * AT_KS + ks + tid4 + 4]);
                MMA_TF32(cs[nt], aq[k4][0], aq[k4][1], aq[k4][2], aq[k4][3], b0, b1);
            }
        }

        // mask padded keys on last tile (keys 300..319)
        if (kt == 4) {
#pragma unroll
            for (int nt = 0; nt < 8; nt++) {
                int col = 256 + nt * 8 + 2 * tid4;
                if (col >= QLEN)     { cs[nt][0] = -1e30f; cs[nt][2] = -1e30f; }
                if (col + 1 >= QLEN) { cs[nt][1] = -1e30f; cs[nt][3] = -1e30f; }
            }
        }

        // row max (2 rows per lane)
        float t0 = -1e30f, t1 = -1e30f;
#pragma unroll
        for (int nt = 0; nt < 8; nt++) {
            t0 = fmaxf(t0, fmaxf(cs[nt][0], cs[nt][1]));
            t1 = fmaxf(t1, fmaxf(cs[nt][2], cs[nt][3]));
        }
#pragma unroll
        for (int off = 1; off <= 2; off <<= 1) {
            t0 = fmaxf(t0, __shfl_xor_sync(0xffffffffu, t0, off));
            t1 = fmaxf(t1, __shfl_xor_sync(0xffffffffu, t1, off));
        }
        float nm0 = fmaxf(m0, t0), nm1 = fmaxf(m1, t1);
        float sc0 = __expf(m0 - nm0), sc1 = __expf(m1 - nm1);
        m0 = nm0; m1 = nm1;

        // exponentiate + row sum
        float s0 = 0.f, s1 = 0.f;
#pragma unroll
        for (int nt = 0; nt < 8; nt++) {
            cs[nt][0] = __expf(cs[nt][0] - nm0);
            cs[nt][1] = __expf(cs[nt][1] - nm0);
            cs[nt][2] = __expf(cs[nt][2] - nm1);
            cs[nt][3] = __expf(cs[nt][3] - nm1);
            s0 += cs[nt][0] + cs[nt][1];
            s1 += cs[nt][2] + cs[nt][3];
        }
#pragma unroll
        for (int off = 1; off <= 2; off <<= 1) {
            s0 += __shfl_xor_sync(0xffffffffu, s0, off);
            s1 += __shfl_xor_sync(0xffffffffu, s1, off);
        }
        l0 = l0 * sc0 + s0;
        l1 = l1 * sc1 + s1;
#pragma unroll
        for (int dt = 0; dt < 4; dt++) {
            co[dt][0] *= sc0; co[dt][1] *= sc0;
            co[dt][2] *= sc1; co[dt][3] *= sc1;
        }

        // O += P @ V  (A-frags rebuilt from accumulator via shuffles)
        int L1 = (gid << 2) | (tid4 >> 1);
        int L2 = L1 + 2;
        bool odd = tid4 & 1;
#pragma unroll
        for (int kk = 0; kk < 8; kk++) {
            float p00 = __shfl_sync(0xffffffffu, cs[kk][0], L1);
            float p01 = __shfl_sync(0xffffffffu, cs[kk][1], L1);
            float p10 = __shfl_sync(0xffffffffu, cs[kk][2], L1);
            float p11 = __shfl_sync(0xffffffffu, cs[kk][3], L1);
            float q00 = __shfl_sync(0xffffffffu, cs[kk][0], L2);
            float q01 = __shfl_sync(0xffffffffu, cs[kk][1], L2);
            float q10 = __shfl_sync(0xffffffffu, cs[kk][2], L2);
            float q11 = __shfl_sync(0xffffffffu, cs[kk][3], L2);
            uint32_t a0 = f2tf(odd ? p01 : p00);
            uint32_t a1 = f2tf(odd ? p11 : p10);
            uint32_t a2 = f2tf(odd ? q01 : q00);
            uint32_t a3 = f2tf(odd ? q11 : q10);
#pragma unroll
            for (int dt = 0; dt < 4; dt++) {
                int d = dt * 8 + gid;
                uint32_t b0 = f2tf(Vs[(kk * 8 + tid4) * AT_VS + d]);
                uint32_t b1 = f2tf(Vs[(kk * 8 + tid4 + 4) * AT_VS + d]);
                MMA_TF32(co[dt], a0, a1, a2, a3, b0, b1);
            }
        }
    }

    // write output
    float il0 = 1.f / l0, il1 = 1.f / l1;
    int q0 = qt * 64 + w * 16 + gid;
    int q1 = q0 + 8;
#pragma unroll
    for (int dt = 0; dt < 4; dt++) {
        int d = h * HD + dt * 8 + 2 * tid4;
        if (q0 < QLEN) {
            float2 v; v.x = co[dt][0] * il0; v.y = co[dt][1] * il0;
            *(float2*)&O[(long)(b * QLEN + q0) * D + d] = v;
        }
        if (q1 < QLEN) {
            float2 v; v.x = co[dt][2] * il1; v.y = co[dt][3] * il1;
            *(float2*)&O[(long)(b * QLEN + q1) * D + d] = v;
        }
    }
}

// ---------------- layernorm helpers ------------------------------------------
__device__ __forceinline__ float block_sum256(float v) {
    __shared__ float sh[8];
#pragma unroll
    for (int off = 16; off > 0; off >>= 1)
        v += __shfl_xor_sync(0xffffffffu, v, off);
    int t = threadIdx.x;
    if ((t & 31) == 0) sh[t >> 5] = v;
    __syncthreads();
    if (t == 0) {
        float s = 0.f;
        for (int i = 0; i < 8; i++) s += sh[i];
        sh[0] = s;
    }
    __syncthreads();
    float r = sh[0];
    __syncthreads();
    return r;
}

__device__ __forceinline__ void ln_write(float x, const float* w, const float* bb,
                                         float* O, int row) {
    int t = threadIdx.x;
    float mean = block_sum256(x) * (1.f / D);
    float d_ = x - mean;
    float var = block_sum256(d_ * d_) * (1.f / D);
    O[(long)row * D + t] = d_ * rsqrtf(var + LN_EPS) * w[t] + bb[t];
}

__global__ void ln_add(const float* __restrict__ A, const float* __restrict__ Bv,
                       const float* __restrict__ w, const float* __restrict__ bb,
                       float* __restrict__ O) {
    int row = blockIdx.x, t = threadIdx.x;
    float x = A[(long)row * D + t] + Bv[(long)row * D + t];
    ln_write(x, w, bb, O, row);
}

__global__ void gate_ln(const float* __restrict__ gates, const float* __restrict__ res,
                        const float* __restrict__ ca, const float* __restrict__ w,
                        const float* __restrict__ bb, float* __restrict__ O) {
    int row = blockIdx.x, t = threadIdx.x;
    float g1 = gates[(long)row * 512 + t];
    float g2 = gates[(long)row * 512 + 256 + t];
    float x = g1 * res[(long)row * D + t] + g2 * ca[(long)row * D + t];
    ln_write(x, w, bb, O, row);
}

// ---------------- aw softmax over SP=12 --------------------------------------
__global__ void softmax12(const float* __restrict__ in, float* __restrict__ out, int rows) {
    int r = blockIdx.x * blockDim.x + threadIdx.x;
    if (r >= rows) return;
    const float* p = in + (long)r * SP;
    float* o = out + (long)r * SP;
    float mx = -1e30f;
#pragma unroll
    for (int i = 0; i < SP; i++) mx = fmaxf(mx, p[i]);
    float e[SP], s = 0.f;
#pragma unroll
    for (int i = 0; i < SP; i++) { e[i] = __expf(p[i] - mx); s += e[i]; }
    float inv = 1.f / s;
#pragma unroll
    for (int i = 0; i < SP; i++) o[i] = e[i] * inv;
}

// ---------------- deformable bilinear sampling -------------------------------
__global__ void sample_kernel(const float* __restrict__ enc, const float* __restrict__ ref,
                              const float* __restrict__ offs, const float* __restrict__ aw,
                              float* __restrict__ ca) {
    int bq = blockIdx.x;
    int b = bq / QLEN;
    int t = threadIdx.x;
    int h = t >> 5, lane = t & 31;
    const float* rp = ref + (long)bq * 4;
    float rx = rp[0], ry = rp[1], rw = rp[2], rh = rp[3];
    const float* op = offs + (long)bq * 192 + h * 24;
    const float* ap = aw + (long)bq * 96 + h * 12;
    const float* eb = enc + (long)b * S_TOT * D + h * HD + lane;
    float acc = 0.f;
#pragma unroll
    for (int p = 0; p < SP; p++) {
        int lvl = p >> 2;
        int Wl = (lvl == 0) ? 80 : (lvl == 1) ? 40 : 20;
        int Hl = Wl;
        int s0 = (lvl == 0) ? 0 : (lvl == 1) ? 6400 : 8000;
        float ox = op[p * 2], oy = op[p * 2 + 1];
        float a = ap[p];
        float gx = (rx + ox * 0.125f * rw) * (float)Wl - 0.5f;
        float gy = (ry + oy * 0.125f * rh) * (float)Hl - 0.5f;
        float x0f = floorf(gx), y0f = floorf(gy);
        float fx = gx - x0f, fy = gy - y0f;
        int x0 = (int)x0f, y0 = (int)y0f;
        int x1 = x0 + 1, y1 = y0 + 1;
        float w00 = (1.f - fx) * (1.f - fy) * a;
        float w10 = fx * (1.f - fy) * a;
        float w01 = (1.f - fx) * fy * a;
        float w11 = fx * fy * a;
        bool vx0 = (x0 >= 0) & (x0 < Wl), vx1 = (x1 >= 0) & (x1 < Wl);
        bool vy0 = (y0 >= 0) & (y0 < Hl), vy1 = (y1 >= 0) & (y1 < Hl);
        if (vx0 & vy0) acc += w00 * eb[(long)(s0 + y0 * Wl + x0) * D];
        if (vx1 & vy0) acc += w10 * eb[(long)(s0 + y0 * Wl + x1) * D];
        if (vx0 & vy1) acc += w01 * eb[(long)(s0 + y1 * Wl + x0) * D];
        if (vx1 & vy1) acc += w11 * eb[(long)(s0 + y1 * Wl + x1) * D];
    }
    ca[(long)bq * D + h * HD + lane] = acc;
}

// ---------------- host orchestration -----------------------------------------
static void launch_gemm(const float* A, const float* B, const float* bias, float* C,
                        int M, int N, int K, float alpha, int act) {
    dim3 grid((N + TN - 1) / TN, M / TM);
    tgemm<<<grid, 256, GEMM_SMEM_BYTES>>>(A, B, bias, C, M, N, K, alpha, act);
}

extern "C" void kernel_launch(void* const* d_in, const int* in_sizes, int n_in,
                              void* d_out, int out_size) {
    const float* hs    = (const float*)d_in[0];
    const float* pos   = (const float*)d_in[1];
    const float* ref   = (const float*)d_in[2];
    const float* enc   = (const float*)d_in[3];
    const float* q_w   = (const float*)d_in[4];
    const float* q_b   = (const float*)d_in[5];
    const float* k_w   = (const float*)d_in[6];
    const float* k_b   = (const float*)d_in[7];
    const float* v_w   = (const float*)d_in[8];
    const float* v_b   = (const float*)d_in[9];
    const float* o_w   = (const float*)d_in[10];
    const float* o_b   = (const float*)d_in[11];
    const float* sa_ln_w = (const float*)d_in[12];
    const float* sa_ln_b = (const float*)d_in[13];
    const float* off_w = (const float*)d_in[14];
    const float* off_b = (const float*)d_in[15];
    const float* aw_w  = (const float*)d_in[16];
    const float* aw_b  = (const float*)d_in[17];
    const float* gate_w = (const float*)d_in[18];
    const float* gate_b = (const float*)d_in[19];
    const float* gate_ln_w = (const float*)d_in[20];
    const float* gate_ln_b = (const float*)d_in[21];
    const float* fc1_w = (const float*)d_in[22];
    const float* fc1_b = (const float*)d_in[23];
    const float* fc2_w = (const float*)d_in[24];
    const float* fc2_b = (const float*)d_in[25];
    const float* fin_ln_w = (const float*)d_in[26];
    const float* fin_ln_b = (const float*)d_in[27];
    float* out = (float*)d_out;

    float *p_hq, *p_q, *p_k, *p_v, *p_attn, *p_res, *p_offs, *p_awl, *p_aw,
          *p_ca, *p_cat, *p_gates, *p_h2, *p_ffn1, *p_ffn2;
    cudaGetSymbolAddress((void**)&p_hq, g_hq);
    cudaGetSymbolAddress((void**)&p_q, g_q);
    cudaGetSymbolAddress((void**)&p_k, g_k);
    cudaGetSymbolAddress((void**)&p_v, g_v);
    cudaGetSymbolAddress((void**)&p_attn, g_attn);
    cudaGetSymbolAddress((void**)&p_res, g_res);
    cudaGetSymbolAddress((void**)&p_offs, g_offs);
    cudaGetSymbolAddress((void**)&p_awl, g_awl);
    cudaGetSymbolAddress((void**)&p_aw, g_aw);
    cudaGetSymbolAddress((void**)&p_ca, g_ca);
    cudaGetSymbolAddress((void**)&p_cat, g_cat);
    cudaGetSymbolAddress((void**)&p_gates, g_gates);
    cudaGetSymbolAddress((void**)&p_h2, g_h2);
    cudaGetSymbolAddress((void**)&p_ffn1, g_ffn1);
    cudaGetSymbolAddress((void**)&p_ffn2, g_ffn2);

    cudaFuncSetAttribute(tgemm, cudaFuncAttributeMaxDynamicSharedMemorySize,
                         GEMM_SMEM_BYTES);

    const float scaling = 0.17677669529663687f; // 32^-0.5
    dim3 blk(256);

    // hq = hs + pos
    add_kernel<<<BQ * D / 256, blk>>>(hs, pos, p_hq, BQ * D);

    // q/k/v projections
    launch_gemm(p_hq, q_w, q_b, p_q, BQ, D, D, scaling, 0);
    launch_gemm(p_hq, k_w, k_b, p_k, BQ, D, D, 1.f, 0);
    launch_gemm(hs,   v_w, v_b, p_v, BQ, D, D, 1.f, 0);

    // self-attention (tensor-core flash)
    flash_attn<<<dim3(5, BATCH * NH), 128>>>(p_q, p_k, p_v, p_attn);

    // o projection + residual LN
    launch_gemm(p_attn, o_w, o_b, p_hq, BQ, D, D, 1.f, 0);
    ln_add<<<BQ, blk>>>(hs, p_hq, sa_ln_w, sa_ln_b, p_res);

    // deformable projections
    launch_gemm(p_res, off_w, off_b, p_offs, BQ, 192, D, 1.f, 0);
    launch_gemm(p_res, aw_w, aw_b, p_awl, BQ, 96, D, 1.f, 0);
    softmax12<<<(BQ * NH + 255) / 256, blk>>>(p_awl, p_aw, BQ * NH);

    // bilinear sampling -> ca
    sample_kernel<<<BQ, blk>>>(enc, ref, p_offs, p_aw, p_ca);

    // gate
    concat_kernel<<<BQ * 512 / 256, blk>>>(p_res, p_ca, p_cat, BQ);
    launch_gemm(p_cat, gate_w, gate_b, p_gates, BQ, 512, 512, 1.f, 2);
    gate_ln<<<BQ, blk>>>(p_gates, p_res, p_ca, gate_ln_w, gate_ln_b, p_h2);

    // FFN
    launch_gemm(p_h2, fc1_w, fc1_b, p_ffn1, BQ, FF, D, 1.f, 1);
    launch_gemm(p_ffn1, fc2_w, fc2_b, p_ffn2, BQ, D, FF, 1.f, 0);

    // final LN -> out
    ln_add<<<BQ, blk>>>(p_h2, p_ffn2, fin_ln_w, fin_ln_b, out);
}